// round 5
// baseline (speedup 1.0000x reference)
#include <cuda_runtime.h>
#include <cuda_bf16.h>
#include <cstdint>

#define NN      50000
#define EE      800000
#define ETOT    (EE + NN)        // edges + self loops
#define IN_CH   256
#define HIDC    64
#define HEADS   2
#define C1      (HEADS * HIDC)   // 128
#define BN_EPS  1e-5f

// ---------------- scratch (static device arrays; no allocation) --------------
__device__ float g_xl1[NN * C1];
__device__ float g_xr1[NN * C1];
__device__ float g_sum1[NN * HEADS];
__device__ float g_h1 [NN * C1];     // layer-1: accumulates sum(p * xl)
__device__ float g_hm [NN * C1];     // after bn1 + elu
__device__ float g_xl2[NN * HIDC];
__device__ float g_xr2[NN * HIDC];
__device__ float g_sum2[NN];
__device__ float g_h2 [NN * HIDC];   // layer-2: accumulates sum(p * xl)

// ---------------- helpers ----------------------------------------------------
typedef unsigned long long u64;

__device__ __forceinline__ float lrelu(float v) { return v > 0.f ? v : 0.2f * v; }

__device__ __forceinline__ void red_add_v4(float* addr, float4 v) {
    asm volatile("red.global.add.v4.f32 [%0], {%1, %2, %3, %4};"
                 :: "l"(addr), "f"(v.x), "f"(v.y), "f"(v.z), "f"(v.w) : "memory");
}

__device__ __forceinline__ u64 pack2(float lo, float hi) {
    u64 r;
    asm("mov.b64 %0, {%1, %2};" : "=l"(r) : "f"(lo), "f"(hi));
    return r;
}
__device__ __forceinline__ void ffma2(u64& acc, u64 a, u64 b) {
    asm("fma.rn.f32x2 %0, %1, %2, %0;" : "+l"(acc) : "l"(a), "l"(b));
}
__device__ __forceinline__ float2 unpack2(u64 v) {
    float lo, hi;
    asm("mov.b64 {%0, %1}, %2;" : "=f"(lo), "=f"(hi) : "l"(v));
    return make_float2(lo, hi);
}
__device__ __forceinline__ void cp_async16(void* smem_ptr, const void* gptr) {
    uint32_t s = (uint32_t)__cvta_generic_to_shared(smem_ptr);
    asm volatile("cp.async.cg.shared.global [%0], [%1], 16;" :: "r"(s), "l"(gptr));
}
__device__ __forceinline__ void cp_commit() {
    asm volatile("cp.async.commit_group;");
}
__device__ __forceinline__ void cp_wait0() {
    asm volatile("cp.async.wait_group 0;");
}

// ---------------- dual GEMM: outl = X@Wl+bl, outr = X@Wr+br ------------------
// K-pair-packed FFMA2: each b64 accumulator holds (sum over even k, sum over
// odd k); final result = lo + hi. X tile is row-major in smem (conflict-free
// staging, broadcast b64 reads). W is cp.async double-buffered in 16-row
// chunks (both matrices side by side: ws[kl][0..2M)).
// blockDim = (M/2)*4: thread = (quad, rg); tile = 32 rows; thread owns
// 4 adjacent cols x 8 rows.
template<int K, int M, int CHUNK>
__device__ __forceinline__ void dual_gemm_body(
    const float* __restrict__ X,
    const float* __restrict__ Wl, const float* __restrict__ bl,
    const float* __restrict__ Wr, const float* __restrict__ br,
    float* __restrict__ outl, float* __restrict__ outr, int n)
{
    constexpr int QUADS = M / 2;        // col-quads across both matrices (2M/4)
    constexpr int RG    = 4;
    constexpr int NT    = QUADS * RG;   // blockDim
    constexpr int NCH   = K / CHUNK;

    extern __shared__ float sm[];
    float* xs = sm;                     // [32][K] row-major
    float* ws = sm + 32 * K;            // [2][CHUNK][2M]

    const int tid = threadIdx.x;
    const int r0  = blockIdx.x * 32;

    // ---- stage X tile (coalesced, conflict-free, zero-pad OOB rows) ----
    for (int i = tid * 4; i < 32 * K; i += NT * 4) {
        int row = i / K, kk = i % K;
        float4 v = make_float4(0.f, 0.f, 0.f, 0.f);
        if (r0 + row < n) v = *(const float4*)&X[(size_t)(r0 + row) * K + kk];
        *(float4*)&xs[row * K + kk] = v;
    }

    // ---- W chunk issue (cp.async) ----
    auto issue = [&](int ch) {
        const int k0 = ch * CHUNK;
        float* dst = ws + (ch & 1) * (CHUNK * 2 * M);
        for (int u = tid * 4; u < CHUNK * 2 * M; u += NT * 4) {
            int kl = u / (2 * M), c = u % (2 * M);
            const float* src = (c < M) ? &Wl[(size_t)(k0 + kl) * M + c]
                                       : &Wr[(size_t)(k0 + kl) * M + (c - M)];
            cp_async16(&dst[u], src);
        }
        cp_commit();
    };
    issue(0);
    __syncthreads();      // xs visible to all

    const int quad = tid % QUADS;
    const int rg   = tid / QUADS;       // uniform within a warp
    const int c0   = quad * 4;
    const int mat  = (c0 >= M) ? 1 : 0;
    const int wc   = c0 & (M - 1);
    const int rb   = rg * 8;

    u64 acc[8][4];
#pragma unroll
    for (int r = 0; r < 8; r++)
#pragma unroll
        for (int j = 0; j < 4; j++) acc[r][j] = 0ULL;

    for (int ch = 0; ch < NCH; ch++) {
        cp_wait0();
        __syncthreads();                 // chunk ready + prev buffer free
        if (ch + 1 < NCH) issue(ch + 1);

        const float* wb_ = ws + (ch & 1) * (CHUNK * 2 * M);
        const int kg = ch * CHUNK;
#pragma unroll
        for (int kp = 0; kp < CHUNK / 2; kp++) {
            const int kl = 2 * kp;
            float4 wa = *(const float4*)&wb_[kl * 2 * M + c0];         // w_k
            float4 wb2 = *(const float4*)&wb_[(kl + 1) * 2 * M + c0];  // w_{k+1}
            u64 w0 = pack2(wa.x, wb2.x);
            u64 w1 = pack2(wa.y, wb2.y);
            u64 w2 = pack2(wa.z, wb2.z);
            u64 w3 = pack2(wa.w, wb2.w);
#pragma unroll
            for (int r = 0; r < 8; r++) {
                u64 xv = *(const u64*)&xs[(rb + r) * K + kg + kl];     // broadcast
                ffma2(acc[r][0], xv, w0);
                ffma2(acc[r][1], xv, w1);
                ffma2(acc[r][2], xv, w2);
                ffma2(acc[r][3], xv, w3);
            }
        }
    }

    float* __restrict__ out = mat ? outr : outl;
    const float* __restrict__ bs = mat ? br : bl;
    float4 bi = *(const float4*)&bs[wc];
#pragma unroll
    for (int r = 0; r < 8; r++) {
        int row = r0 + rb + r;
        if (row < n) {
            float2 a0 = unpack2(acc[r][0]);
            float2 a1 = unpack2(acc[r][1]);
            float2 a2 = unpack2(acc[r][2]);
            float2 a3 = unpack2(acc[r][3]);
            float4 o = make_float4(a0.x + a0.y + bi.x, a1.x + a1.y + bi.y,
                                   a2.x + a2.y + bi.z, a3.x + a3.y + bi.w);
            *(float4*)&out[(size_t)row * M + wc] = o;
        }
    }
}

__global__ __launch_bounds__(256) void k_gemm1(
    const float* __restrict__ X,
    const float* __restrict__ Wl, const float* __restrict__ bl,
    const float* __restrict__ Wr, const float* __restrict__ br)
{
    dual_gemm_body<IN_CH, C1, 16>(X, Wl, bl, Wr, br, g_xl1, g_xr1, NN);
}

// gemm2 also re-zeros g_sum1 (consumed by k_epi1 just before; next reader is
// edge1 of the NEXT launch — race-free).
__global__ __launch_bounds__(128) void k_gemm2(
    const float* __restrict__ Wl, const float* __restrict__ bl,
    const float* __restrict__ Wr, const float* __restrict__ br)
{
    int gid = blockIdx.x * blockDim.x + threadIdx.x;
    if (gid < NN * HEADS) g_sum1[gid] = 0.f;
    dual_gemm_body<C1, HIDC, 16>(g_hm, Wl, bl, Wr, br, g_xl2, g_xr2, NN);
}

// ---------------- layer-1 FUSED edge pass ------------------------------------
// warp per edge; lane handles 4 channels of 128 (lanes 0-15 head0, 16-31 head1).
__global__ void k_edge1(const int* __restrict__ ei, const float* __restrict__ att)
{
    int warp = (blockIdx.x * blockDim.x + threadIdx.x) >> 5;
    int lane = threadIdx.x & 31;
    if (warp >= ETOT) return;

    int src, dst;
    if (warp < EE) { src = ei[warp]; dst = ei[EE + warp]; }
    else           { src = dst = warp - EE; }

    int c = lane * 4;
    float4 a  = *(const float4*)&g_xl1[(size_t)src * C1 + c];
    float4 b  = *(const float4*)&g_xr1[(size_t)dst * C1 + c];
    float4 at = *(const float4*)&att[c];

    float s = at.x * lrelu(a.x + b.x)
            + at.y * lrelu(a.y + b.y)
            + at.z * lrelu(a.z + b.z)
            + at.w * lrelu(a.w + b.w);

    s += __shfl_xor_sync(0xffffffffu, s, 8);
    s += __shfl_xor_sync(0xffffffffu, s, 4);
    s += __shfl_xor_sync(0xffffffffu, s, 2);
    s += __shfl_xor_sync(0xffffffffu, s, 1);

    float p = __expf(s);

    if ((lane & 15) == 0)
        atomicAdd(&g_sum1[(size_t)dst * 2 + (lane >> 4)], p);

    float4 v = make_float4(a.x * p, a.y * p, a.z * p, a.w * p);
    red_add_v4(&g_h1[(size_t)dst * C1 + c], v);
}

// ---------------- layer-1 epilogue: /sum, +bias, bn, elu (float4) ------------
__global__ void k_epi1(const float* __restrict__ bias,
                       const float* __restrict__ bg, const float* __restrict__ bb,
                       const float* __restrict__ bm, const float* __restrict__ bv)
{
    int i4 = (blockIdx.x * blockDim.x + threadIdx.x) * 4;
    if (i4 >= NN * C1) return;
    int c    = i4 & (C1 - 1);
    int node = i4 >> 7;                   // C1 == 128
    int h    = c >> 6;
    float inv_s = __fdividef(1.f, g_sum1[node * 2 + h]);

    float4 hv = *(const float4*)&g_h1[i4];
    float4 bi = *(const float4*)&bias[c];
    float4 gm = *(const float4*)&bg[c];
    float4 bt = *(const float4*)&bb[c];
    float4 mu = *(const float4*)&bm[c];
    float4 vr = *(const float4*)&bv[c];

    float x0 = (hv.x * inv_s + bi.x - mu.x) * rsqrtf(vr.x + BN_EPS) * gm.x + bt.x;
    float x1 = (hv.y * inv_s + bi.y - mu.y) * rsqrtf(vr.y + BN_EPS) * gm.y + bt.y;
    float x2 = (hv.z * inv_s + bi.z - mu.z) * rsqrtf(vr.z + BN_EPS) * gm.z + bt.z;
    float x3 = (hv.w * inv_s + bi.w - mu.w) * rsqrtf(vr.w + BN_EPS) * gm.w + bt.w;

    float4 o;
    o.x = x0 > 0.f ? x0 : expm1f(x0);
    o.y = x1 > 0.f ? x1 : expm1f(x1);
    o.z = x2 > 0.f ? x2 : expm1f(x2);
    o.w = x3 > 0.f ? x3 : expm1f(x3);
    *(float4*)&g_hm[i4] = o;
    *(float4*)&g_h1[i4] = make_float4(0.f, 0.f, 0.f, 0.f);
}

// ---------------- layer-2 FUSED edge pass (heads=1, 64ch, 16 lanes/edge) -----
__global__ void k_edge2(const int* __restrict__ ei, const float* __restrict__ att)
{
    int gid  = blockIdx.x * blockDim.x + threadIdx.x;
    int e    = gid >> 4;                   // 16 lanes per edge
    int l    = gid & 15;
    if (e >= ETOT) return;

    int src, dst;
    if (e < EE) { src = ei[e]; dst = ei[EE + e]; }
    else        { src = dst = e - EE; }

    int c = l * 4;
    float4 a  = *(const float4*)&g_xl2[(size_t)src * HIDC + c];
    float4 b  = *(const float4*)&g_xr2[(size_t)dst * HIDC + c];
    float4 at = *(const float4*)&att[c];

    float s = at.x * lrelu(a.x + b.x)
            + at.y * lrelu(a.y + b.y)
            + at.z * lrelu(a.z + b.z)
            + at.w * lrelu(a.w + b.w);

    s += __shfl_xor_sync(0xffffffffu, s, 8);
    s += __shfl_xor_sync(0xffffffffu, s, 4);
    s += __shfl_xor_sync(0xffffffffu, s, 2);
    s += __shfl_xor_sync(0xffffffffu, s, 1);

    float p = __expf(s);

    if (l == 0)
        atomicAdd(&g_sum2[dst], p);

    float4 v = make_float4(a.x * p, a.y * p, a.z * p, a.w * p);
    red_add_v4(&g_h2[(size_t)dst * HIDC + c], v);
}

// ---------------- final: /sum, +bias2, bn2, elu, classifier, sigmoid ---------
__global__ void k_final(const float* __restrict__ bias,
                        const float* __restrict__ bg, const float* __restrict__ bb,
                        const float* __restrict__ bm, const float* __restrict__ bv,
                        const float* __restrict__ Wc, const float* __restrict__ bc,
                        float* __restrict__ out)
{
    int warp = (blockIdx.x * blockDim.x + threadIdx.x) >> 5;
    int lane = threadIdx.x & 31;
    if (warp >= NN) return;

    float inv_s = __fdividef(1.f, g_sum2[warp]);
    int c = lane * 2;
    float2 h  = *(const float2*)&g_h2[(size_t)warp * HIDC + c];
    float x0 = h.x * inv_s + bias[c + 0];
    float x1 = h.y * inv_s + bias[c + 1];
    x0 = (x0 - bm[c + 0]) * rsqrtf(bv[c + 0] + BN_EPS) * bg[c + 0] + bb[c + 0];
    x1 = (x1 - bm[c + 1]) * rsqrtf(bv[c + 1] + BN_EPS) * bg[c + 1] + bb[c + 1];
    x0 = x0 > 0.f ? x0 : expm1f(x0);
    x1 = x1 > 0.f ? x1 : expm1f(x1);

    // restore zero state for next replay
    *(float2*)&g_h2[(size_t)warp * HIDC + c] = make_float2(0.f, 0.f);
    if (lane == 0) g_sum2[warp] = 0.f;

    float z = x0 * Wc[c + 0] + x1 * Wc[c + 1];
    z += __shfl_xor_sync(0xffffffffu, z, 16);
    z += __shfl_xor_sync(0xffffffffu, z, 8);
    z += __shfl_xor_sync(0xffffffffu, z, 4);
    z += __shfl_xor_sync(0xffffffffu, z, 2);
    z += __shfl_xor_sync(0xffffffffu, z, 1);

    if (lane == 0) {
        z += bc[0];
        out[warp] = 1.f / (1.f + __expf(-z));
    }
}

// ---------------- launch -----------------------------------------------------
extern "C" void kernel_launch(void* const* d_in, const int* in_sizes, int n_in,
                              void* d_out, int out_size)
{
    const float* x    = (const float*)d_in[0];
    const int*   ei   = (const int*)  d_in[1];
    const float* W1l  = (const float*)d_in[2];
    const float* b1l  = (const float*)d_in[3];
    const float* W1r  = (const float*)d_in[4];
    const float* b1r  = (const float*)d_in[5];
    const float* att1 = (const float*)d_in[6];
    const float* bias1= (const float*)d_in[7];
    const float* bn1g = (const float*)d_in[8];
    const float* bn1b = (const float*)d_in[9];
    const float* bn1m = (const float*)d_in[10];
    const float* bn1v = (const float*)d_in[11];
    const float* W2l  = (const float*)d_in[12];
    const float* b2l  = (const float*)d_in[13];
    const float* W2r  = (const float*)d_in[14];
    const float* b2r  = (const float*)d_in[15];
    const float* att2 = (const float*)d_in[16];
    const float* bias2= (const float*)d_in[17];
    const float* bn2g = (const float*)d_in[18];
    const float* bn2b = (const float*)d_in[19];
    const float* bn2m = (const float*)d_in[20];
    const float* bn2v = (const float*)d_in[21];
    const float* Wc   = (const float*)d_in[22];
    const float* bc   = (const float*)d_in[23];
    float* out = (float*)d_out;

    const int edge1Blocks = (ETOT * 32 + 255) / 256;   // warp per edge
    const int edge2Blocks = (ETOT * 16 + 255) / 256;   // 16 lanes per edge
    const int rowBlocks   = (NN + 31) / 32;

    // dynamic smem: xs[32][K] + ws[2][16][2M]
    const int smem1 = (32 * IN_CH + 2 * 16 * 2 * C1)   * sizeof(float);  // 64 KB
    const int smem2 = (32 * C1    + 2 * 16 * 2 * HIDC) * sizeof(float);  // 32 KB
    static bool attr_set = false;
    if (!attr_set) {
        cudaFuncSetAttribute(k_gemm1, cudaFuncAttributeMaxDynamicSharedMemorySize, smem1);
        cudaFuncSetAttribute(k_gemm2, cudaFuncAttributeMaxDynamicSharedMemorySize, smem2);
        attr_set = true;
    }

    // layer 1
    k_gemm1<<<rowBlocks, 256, smem1>>>(x, W1l, b1l, W1r, b1r);
    k_edge1<<<edge1Blocks, 256>>>(ei, att1);
    k_epi1<<<(NN * C1 / 4 + 255) / 256, 256>>>(bias1, bn1g, bn1b, bn1m, bn1v);

    // layer 2
    k_gemm2<<<rowBlocks, 128, smem2>>>(W2l, b2l, W2r, b2r);
    k_edge2<<<edge2Blocks, 256>>>(ei, att2);

    // epilogue + classifier
    k_final<<<(NN * 32 + 255) / 256, 256>>>(bias2, bn2g, bn2b, bn2m, bn2v, Wc, bc, out);
}

// round 6
// speedup vs baseline: 1.1188x; 1.1188x over previous
#include <cuda_runtime.h>
#include <cuda_fp16.h>
#include <cstdint>

#define NN      50000
#define EE      800000
#define ETOT    (EE + NN)        // edges + self loops
#define IN_CH   256
#define HIDC    64
#define HEADS   2
#define C1      (HEADS * HIDC)   // 128
#define BN_EPS  1e-5f

// ---------------- scratch (static device arrays; no allocation) --------------
__device__ __half g_xl1h[NN * C1];   // fp16 edge operands (gather traffic /2)
__device__ __half g_xr1h[NN * C1];
__device__ float  g_sum1[NN * HEADS];
__device__ float  g_h1 [NN * C1];    // layer-1: accumulates sum(p * xl), fp32
__device__ float  g_hm [NN * C1];    // after bn1 + elu
__device__ __half g_xl2h[NN * HIDC];
__device__ __half g_xr2h[NN * HIDC];
__device__ float  g_sum2[NN];
__device__ float  g_h2 [NN * HIDC];  // layer-2: accumulates sum(p * xl), fp32

// ---------------- helpers ----------------------------------------------------
typedef unsigned long long u64;

__device__ __forceinline__ float lrelu(float v) { return v > 0.f ? v : 0.2f * v; }

__device__ __forceinline__ void red_add_v4(float* addr, float4 v) {
    asm volatile("red.global.add.v4.f32 [%0], {%1, %2, %3, %4};"
                 :: "l"(addr), "f"(v.x), "f"(v.y), "f"(v.z), "f"(v.w) : "memory");
}

// packed f32x2 helpers (FFMA2 — only reachable via PTX on sm_103a)
__device__ __forceinline__ u64 bcast2(float w) {
    u64 r;
    asm("mov.b64 %0, {%1, %1};" : "=l"(r) : "f"(w));
    return r;
}
__device__ __forceinline__ void ffma2(u64& acc, u64 a, u64 b) {
    asm("fma.rn.f32x2 %0, %1, %2, %0;" : "+l"(acc) : "l"(a), "l"(b));
}
__device__ __forceinline__ float2 unpack2(u64 v) {
    float lo, hi;
    asm("mov.b64 {%0, %1}, %2;" : "=f"(lo), "=f"(hi) : "l"(v));
    return make_float2(lo, hi);
}

// ---------------- dual GEMM with packed f32x2 FMA (R3 structure) -------------
// Tile: 32 rows x 2M cols. blockDim = M. Thread t owns 2 adjacent cols.
// X tile staged k-major in smem (pad 36). Outputs written as fp16.
template<int K, int M>
__device__ __forceinline__ void dual_gemm_f32x2(
    const float* __restrict__ X,
    const float* __restrict__ Wl, const float* __restrict__ bl,
    const float* __restrict__ Wr, const float* __restrict__ br,
    __half* __restrict__ outl, __half* __restrict__ outr, int n)
{
    constexpr int PAD = 36;
    __shared__ __align__(16) float xs[K * PAD];   // xs[k*PAD + row]
    const int t  = threadIdx.x;                   // 0..M-1
    const int r0 = blockIdx.x * 32;

    // stage X tile transposed (zero-pad OOB rows)
    for (int i = t * 4; i < 32 * K; i += M * 4) {
        int row = i / K, kk = i % K;
        float4 v = make_float4(0.f, 0.f, 0.f, 0.f);
        if (r0 + row < n) v = *(const float4*)&X[(size_t)(r0 + row) * K + kk];
        xs[(kk + 0) * PAD + row] = v.x;
        xs[(kk + 1) * PAD + row] = v.y;
        xs[(kk + 2) * PAD + row] = v.z;
        xs[(kk + 3) * PAD + row] = v.w;
    }
    __syncthreads();

    const int c0  = 2 * t;
    const int mat = (c0 >= M) ? 1 : 0;
    const float* __restrict__ W  = mat ? Wr : Wl;
    const float* __restrict__ bs = mat ? br : bl;
    const int wc = c0 & (M - 1);

    u64 accA[16], accB[16];                       // row-pairs for col wc, wc+1
#pragma unroll
    for (int r = 0; r < 16; r++) { accA[r] = 0ULL; accB[r] = 0ULL; }

#pragma unroll 4
    for (int k = 0; k < K; k++) {
        float2 w = *(const float2*)&W[k * M + wc];
        u64 wA = bcast2(w.x);
        u64 wB = bcast2(w.y);
        const u64* xrow = (const u64*)&xs[k * PAD];
#pragma unroll
        for (int r = 0; r < 16; r++) {
            u64 xv = xrow[r];                     // rows 2r,2r+1 (broadcast LDS)
            ffma2(accA[r], xv, wA);
            ffma2(accB[r], xv, wB);
        }
    }

    __half* __restrict__ out = mat ? outr : outl;
    const float b0 = bs[wc], b1 = bs[wc + 1];
#pragma unroll
    for (int r = 0; r < 16; r++) {
        float2 a = unpack2(accA[r]);
        float2 b = unpack2(accB[r]);
        int row = r0 + 2 * r;
        if (row < n)
            *(__half2*)&out[(size_t)row * M + wc] =
                __floats2half2_rn(a.x + b0, b.x + b1);
        if (row + 1 < n)
            *(__half2*)&out[(size_t)(row + 1) * M + wc] =
                __floats2half2_rn(a.y + b0, b.y + b1);
    }
}

__global__ __launch_bounds__(C1) void k_gemm1(
    const float* __restrict__ X,
    const float* __restrict__ Wl, const float* __restrict__ bl,
    const float* __restrict__ Wr, const float* __restrict__ br)
{
    dual_gemm_f32x2<IN_CH, C1>(X, Wl, bl, Wr, br, g_xl1h, g_xr1h, NN);
}

// gemm2 also re-zeros g_sum1 (consumed by k_epi1 just before; next reader is
// edge1 of the NEXT launch — race-free).
__global__ __launch_bounds__(HIDC) void k_gemm2(
    const float* __restrict__ Wl, const float* __restrict__ bl,
    const float* __restrict__ Wr, const float* __restrict__ br)
{
    for (int gid = blockIdx.x * blockDim.x + threadIdx.x;
         gid < NN * HEADS; gid += gridDim.x * blockDim.x) {}  // (indexing below)
    int gid = blockIdx.x * blockDim.x + threadIdx.x;
    if (gid < NN * HEADS) g_sum1[gid] = 0.f;
    dual_gemm_f32x2<C1, HIDC>(g_hm, Wl, bl, Wr, br, g_xl2h, g_xr2h, NN);
}

// ---------------- layer-1 FUSED edge pass (fp16 gathers, 16 lanes/edge) ------
// lane l (0..15) handles 8 channels: ch = l*8. lanes 0-7 head0, 8-15 head1.
__global__ void k_edge1(const int* __restrict__ ei, const float* __restrict__ att)
{
    int gid = blockIdx.x * blockDim.x + threadIdx.x;
    int e   = gid >> 4;                    // 16 lanes per edge
    int l   = gid & 15;
    if (e >= ETOT) return;

    int src, dst;
    if (e < EE) { src = ei[e]; dst = ei[EE + e]; }
    else        { src = dst = e - EE; }

    int ch = l * 8;
    uint4 ar = *(const uint4*)&g_xl1h[(size_t)src * C1 + ch];  // 8 halves
    uint4 br = *(const uint4*)&g_xr1h[(size_t)dst * C1 + ch];
    const __half2* ah = (const __half2*)&ar;
    const __half2* bh = (const __half2*)&br;

    float4 at0 = *(const float4*)&att[ch];
    float4 at1 = *(const float4*)&att[ch + 4];

    float2 a0 = __half22float2(ah[0]), a1 = __half22float2(ah[1]);
    float2 a2 = __half22float2(ah[2]), a3 = __half22float2(ah[3]);
    float2 b0 = __half22float2(bh[0]), b1 = __half22float2(bh[1]);
    float2 b2 = __half22float2(bh[2]), b3 = __half22float2(bh[3]);

    float s = at0.x * lrelu(a0.x + b0.x) + at0.y * lrelu(a0.y + b0.y)
            + at0.z * lrelu(a1.x + b1.x) + at0.w * lrelu(a1.y + b1.y)
            + at1.x * lrelu(a2.x + b2.x) + at1.y * lrelu(a2.y + b2.y)
            + at1.z * lrelu(a3.x + b3.x) + at1.w * lrelu(a3.y + b3.y);

    // reduce over each 8-lane half (one head each)
    s += __shfl_xor_sync(0xffffffffu, s, 4);
    s += __shfl_xor_sync(0xffffffffu, s, 2);
    s += __shfl_xor_sync(0xffffffffu, s, 1);

    float p = __expf(s);

    if ((l & 7) == 0)
        atomicAdd(&g_sum1[(size_t)dst * 2 + (l >> 3)], p);

    float4 v0 = make_float4(a0.x * p, a0.y * p, a1.x * p, a1.y * p);
    float4 v1 = make_float4(a2.x * p, a2.y * p, a3.x * p, a3.y * p);
    float* hb = &g_h1[(size_t)dst * C1 + ch];
    red_add_v4(hb,     v0);
    red_add_v4(hb + 4, v1);
}

// ---------------- layer-1 epilogue: /sum, +bias, bn, elu (float4) ------------
// Restores g_h1 to zero for next graph replay.
__global__ void k_epi1(const float* __restrict__ bias,
                       const float* __restrict__ bg, const float* __restrict__ bb,
                       const float* __restrict__ bm, const float* __restrict__ bv)
{
    int i4 = (blockIdx.x * blockDim.x + threadIdx.x) * 4;
    if (i4 >= NN * C1) return;
    int c    = i4 & (C1 - 1);
    int node = i4 >> 7;                   // C1 == 128
    int h    = c >> 6;
    float inv_s = __fdividef(1.f, g_sum1[node * 2 + h]);

    float4 hv = *(const float4*)&g_h1[i4];
    float4 bi = *(const float4*)&bias[c];
    float4 gm = *(const float4*)&bg[c];
    float4 bt = *(const float4*)&bb[c];
    float4 mu = *(const float4*)&bm[c];
    float4 vr = *(const float4*)&bv[c];

    float x0 = (hv.x * inv_s + bi.x - mu.x) * rsqrtf(vr.x + BN_EPS) * gm.x + bt.x;
    float x1 = (hv.y * inv_s + bi.y - mu.y) * rsqrtf(vr.y + BN_EPS) * gm.y + bt.y;
    float x2 = (hv.z * inv_s + bi.z - mu.z) * rsqrtf(vr.z + BN_EPS) * gm.z + bt.z;
    float x3 = (hv.w * inv_s + bi.w - mu.w) * rsqrtf(vr.w + BN_EPS) * gm.w + bt.w;

    float4 o;
    o.x = x0 > 0.f ? x0 : expm1f(x0);
    o.y = x1 > 0.f ? x1 : expm1f(x1);
    o.z = x2 > 0.f ? x2 : expm1f(x2);
    o.w = x3 > 0.f ? x3 : expm1f(x3);
    *(float4*)&g_hm[i4] = o;
    *(float4*)&g_h1[i4] = make_float4(0.f, 0.f, 0.f, 0.f);
}

// ---------------- layer-2 FUSED edge pass (fp16, 8 lanes/edge, 64ch) ---------
__global__ void k_edge2(const int* __restrict__ ei, const float* __restrict__ att)
{
    int gid = blockIdx.x * blockDim.x + threadIdx.x;
    int e   = gid >> 3;                    // 8 lanes per edge
    int l   = gid & 7;
    if (e >= ETOT) return;

    int src, dst;
    if (e < EE) { src = ei[e]; dst = ei[EE + e]; }
    else        { src = dst = e - EE; }

    int ch = l * 8;
    uint4 ar = *(const uint4*)&g_xl2h[(size_t)src * HIDC + ch];
    uint4 br = *(const uint4*)&g_xr2h[(size_t)dst * HIDC + ch];
    const __half2* ah = (const __half2*)&ar;
    const __half2* bh = (const __half2*)&br;

    float4 at0 = *(const float4*)&att[ch];
    float4 at1 = *(const float4*)&att[ch + 4];

    float2 a0 = __half22float2(ah[0]), a1 = __half22float2(ah[1]);
    float2 a2 = __half22float2(ah[2]), a3 = __half22float2(ah[3]);
    float2 b0 = __half22float2(bh[0]), b1 = __half22float2(bh[1]);
    float2 b2 = __half22float2(bh[2]), b3 = __half22float2(bh[3]);

    float s = at0.x * lrelu(a0.x + b0.x) + at0.y * lrelu(a0.y + b0.y)
            + at0.z * lrelu(a1.x + b1.x) + at0.w * lrelu(a1.y + b1.y)
            + at1.x * lrelu(a2.x + b2.x) + at1.y * lrelu(a2.y + b2.y)
            + at1.z * lrelu(a3.x + b3.x) + at1.w * lrelu(a3.y + b3.y);

    // reduce over 8-lane group
    s += __shfl_xor_sync(0xffffffffu, s, 4);
    s += __shfl_xor_sync(0xffffffffu, s, 2);
    s += __shfl_xor_sync(0xffffffffu, s, 1);

    float p = __expf(s);

    if (l == 0)
        atomicAdd(&g_sum2[dst], p);

    float4 v0 = make_float4(a0.x * p, a0.y * p, a1.x * p, a1.y * p);
    float4 v1 = make_float4(a2.x * p, a2.y * p, a3.x * p, a3.y * p);
    float* hb = &g_h2[(size_t)dst * HIDC + ch];
    red_add_v4(hb,     v0);
    red_add_v4(hb + 4, v1);
}

// ---------------- final: /sum, +bias2, bn2, elu, classifier, sigmoid ---------
// Restores g_h2 / g_sum2 to zero (warp-private, program-order safe).
__global__ void k_final(const float* __restrict__ bias,
                        const float* __restrict__ bg, const float* __restrict__ bb,
                        const float* __restrict__ bm, const float* __restrict__ bv,
                        const float* __restrict__ Wc, const float* __restrict__ bc,
                        float* __restrict__ out)
{
    int warp = (blockIdx.x * blockDim.x + threadIdx.x) >> 5;
    int lane = threadIdx.x & 31;
    if (warp >= NN) return;

    float inv_s = __fdividef(1.f, g_sum2[warp]);
    int c = lane * 2;
    float2 h  = *(const float2*)&g_h2[(size_t)warp * HIDC + c];
    float x0 = h.x * inv_s + bias[c + 0];
    float x1 = h.y * inv_s + bias[c + 1];
    x0 = (x0 - bm[c + 0]) * rsqrtf(bv[c + 0] + BN_EPS) * bg[c + 0] + bb[c + 0];
    x1 = (x1 - bm[c + 1]) * rsqrtf(bv[c + 1] + BN_EPS) * bg[c + 1] + bb[c + 1];
    x0 = x0 > 0.f ? x0 : expm1f(x0);
    x1 = x1 > 0.f ? x1 : expm1f(x1);

    *(float2*)&g_h2[(size_t)warp * HIDC + c] = make_float2(0.f, 0.f);
    if (lane == 0) g_sum2[warp] = 0.f;

    float z = x0 * Wc[c + 0] + x1 * Wc[c + 1];
    z += __shfl_xor_sync(0xffffffffu, z, 16);
    z += __shfl_xor_sync(0xffffffffu, z, 8);
    z += __shfl_xor_sync(0xffffffffu, z, 4);
    z += __shfl_xor_sync(0xffffffffu, z, 2);
    z += __shfl_xor_sync(0xffffffffu, z, 1);

    if (lane == 0) {
        z += bc[0];
        out[warp] = 1.f / (1.f + __expf(-z));
    }
}

// ---------------- launch -----------------------------------------------------
extern "C" void kernel_launch(void* const* d_in, const int* in_sizes, int n_in,
                              void* d_out, int out_size)
{
    const float* x    = (const float*)d_in[0];
    const int*   ei   = (const int*)  d_in[1];
    const float* W1l  = (const float*)d_in[2];
    const float* b1l  = (const float*)d_in[3];
    const float* W1r  = (const float*)d_in[4];
    const float* b1r  = (const float*)d_in[5];
    const float* att1 = (const float*)d_in[6];
    const float* bias1= (const float*)d_in[7];
    const float* bn1g = (const float*)d_in[8];
    const float* bn1b = (const float*)d_in[9];
    const float* bn1m = (const float*)d_in[10];
    const float* bn1v = (const float*)d_in[11];
    const float* W2l  = (const float*)d_in[12];
    const float* b2l  = (const float*)d_in[13];
    const float* W2r  = (const float*)d_in[14];
    const float* b2r  = (const float*)d_in[15];
    const float* att2 = (const float*)d_in[16];
    const float* bias2= (const float*)d_in[17];
    const float* bn2g = (const float*)d_in[18];
    const float* bn2b = (const float*)d_in[19];
    const float* bn2m = (const float*)d_in[20];
    const float* bn2v = (const float*)d_in[21];
    const float* Wc   = (const float*)d_in[22];
    const float* bc   = (const float*)d_in[23];
    float* out = (float*)d_out;

    const int edge1Blocks = (ETOT * 16 + 255) / 256;   // 16 lanes per edge
    const int edge2Blocks = (ETOT * 8  + 255) / 256;   // 8 lanes per edge
    const int rowBlocks   = (NN + 31) / 32;

    // layer 1
    k_gemm1<<<rowBlocks, C1>>>(x, W1l, b1l, W1r, b1r);
    k_edge1<<<edge1Blocks, 256>>>(ei, att1);
    k_epi1<<<(NN * C1 / 4 + 255) / 256, 256>>>(bias1, bn1g, bn1b, bn1m, bn1v);

    // layer 2
    k_gemm2<<<rowBlocks, HIDC>>>(W2l, b2l, W2r, b2r);
    k_edge2<<<edge2Blocks, 256>>>(ei, att2);

    // epilogue + classifier
    k_final<<<(NN * 32 + 255) / 256, 256>>>(bias2, bn2g, bn2b, bn2m, bn2v, Wc, bc, out);
}